// round 6
// baseline (speedup 1.0000x reference)
#include <cuda_runtime.h>
#include <cuda_fp16.h>
#include <cstdint>

// ---------------------------------------------------------------------------
// GCNEncoder: 8-layer GCN, N=100000, E=1.6M, F=15->64(x7)->64
// Separate GEMM (fp32 compute, fp16 store) + CSR agg (fp16 gather, fp32 acc).
// Round 6: agg proven LSU-issue-bound -> vectorize edge-list loads
// (int4 indices + float4 norms per 4 edges, alignment-peeled).
// edge_index is int32 on device (JAX default, x64 disabled).
// ---------------------------------------------------------------------------

#define MAXN 131072
#define MAXE 1700000

__device__ __half g_t[MAXN * 64];       // transformed features (fp16 staged)
__device__ float  g_h[MAXN * 64];       // layer activations (fp32)
__device__ float  g_deg[MAXN];
__device__ float  g_dinv[MAXN];
__device__ float  g_selfnorm[MAXN];
__device__ int    g_cnt[MAXN];
__device__ int    g_cursor[MAXN];
__device__ int    g_rowoff[MAXN + 1];
__device__ int    g_bsum[256];
__device__ __align__(16) int   g_esrc[MAXE];
__device__ __align__(16) float g_enorm[MAXE];

// ------------------------------ preprocessing ------------------------------

__global__ void k_init(int N) {
    int i = blockIdx.x * blockDim.x + threadIdx.x;
    if (i < N) {
        g_deg[i] = 1.0f;   // self-loop weight
        g_cnt[i] = 0;
        g_cursor[i] = 0;
    }
}

__global__ void k_edge_deg(const int* __restrict__ ei,
                           const float* __restrict__ ew, int E, int N) {
    int i = blockIdx.x * blockDim.x + threadIdx.x;
    if (i >= E) return;
    int d = ei[E + i];
    if ((unsigned)d >= (unsigned)N) return;
    atomicAdd(&g_deg[d], ew[i]);
    atomicAdd(&g_cnt[d], 1);
}

__global__ void k_dinv(int N) {
    int i = blockIdx.x * blockDim.x + threadIdx.x;
    if (i < N) {
        float dg = g_deg[i];
        float r = (dg > 0.0f) ? rsqrtf(dg) : 0.0f;
        g_dinv[i] = r;
        g_selfnorm[i] = r * r;
    }
}

// scan step A: per-1024-chunk sums
__global__ void k_scan_reduce(int N) {
    __shared__ int sdata[256];
    int b = blockIdx.x;
    int base = b * 1024;
    int sum = 0;
    for (int i = threadIdx.x; i < 1024; i += 256) {
        int g = base + i;
        sum += (g < N) ? g_cnt[g] : 0;
    }
    sdata[threadIdx.x] = sum;
    __syncthreads();
    for (int s = 128; s > 0; s >>= 1) {
        if (threadIdx.x < s) sdata[threadIdx.x] += sdata[threadIdx.x + s];
        __syncthreads();
    }
    if (threadIdx.x == 0) g_bsum[b] = sdata[0];
}

// scan step B: exclusive scan of chunk sums (NB <= 128)
__global__ void k_scan_bsum(int NB, int N, int E) {
    __shared__ int sh[128];
    int t = threadIdx.x;
    if (t < NB) sh[t] = g_bsum[t];
    __syncthreads();
    if (t == 0) {
        int run = 0;
        for (int i = 0; i < NB; i++) { int x = sh[i]; sh[i] = run; run += x; }
    }
    __syncthreads();
    if (t < NB) g_bsum[t] = sh[t];
    if (t == 0) g_rowoff[N] = E;
}

// scan step C: per-chunk exclusive scan + chunk base -> row offsets
__global__ void k_scan_chunks(int N) {
    int b = blockIdx.x;
    int t = threadIdx.x;
    int g0 = b * 1024 + 4 * t;
    int v0 = (g0 + 0 < N) ? g_cnt[g0 + 0] : 0;
    int v1 = (g0 + 1 < N) ? g_cnt[g0 + 1] : 0;
    int v2 = (g0 + 2 < N) ? g_cnt[g0 + 2] : 0;
    int v3 = (g0 + 3 < N) ? g_cnt[g0 + 3] : 0;
    int s = v0 + v1 + v2 + v3;
    int lane = t & 31, wid = t >> 5;
    int incl = s;
#pragma unroll
    for (int o = 1; o < 32; o <<= 1) {
        int x = __shfl_up_sync(0xffffffffu, incl, o);
        if (lane >= o) incl += x;
    }
    __shared__ int wsum[8];
    __shared__ int woff[8];
    if (lane == 31) wsum[wid] = incl;
    __syncthreads();
    if (t == 0) {
        int run = 0;
        for (int i = 0; i < 8; i++) { int x = wsum[i]; woff[i] = run; run += x; }
    }
    __syncthreads();
    int excl = g_bsum[b] + woff[wid] + (incl - s);
    if (g0 + 0 < N) g_rowoff[g0 + 0] = excl;
    if (g0 + 1 < N) g_rowoff[g0 + 1] = excl + v0;
    if (g0 + 2 < N) g_rowoff[g0 + 2] = excl + v0 + v1;
    if (g0 + 3 < N) g_rowoff[g0 + 3] = excl + v0 + v1 + v2;
}

__global__ void k_fill(const int* __restrict__ ei,
                       const float* __restrict__ ew, int E, int N) {
    int i = blockIdx.x * blockDim.x + threadIdx.x;
    if (i >= E) return;
    int s = ei[i];
    int d = ei[E + i];
    if ((unsigned)s >= (unsigned)N || (unsigned)d >= (unsigned)N) return;
    float nm = g_dinv[s] * ew[i] * g_dinv[d];
    int pos = g_rowoff[d] + atomicAdd(&g_cursor[d], 1);
    if ((unsigned)pos < (unsigned)MAXE) {
        g_esrc[pos] = s;
        g_enorm[pos] = nm;
    }
}

// ------------------------------- dense GEMM --------------------------------
// C[N,64] = A[N,FIN] @ W[FIN,64], fp32 compute, fp16 store.
// 64-node tile per block, 4x4 register tile, 256 threads.

template <int FIN>
__global__ void k_transform(const float* __restrict__ A,
                            const float* __restrict__ W,
                            __half* __restrict__ C, int N) {
    __shared__ float As[FIN][68];
    __shared__ float Bs[FIN][68];
    int t = threadIdx.x;                 // 256 threads
    int n0 = blockIdx.x * 64;

    // load W -> Bs
    for (int idx = t; idx < FIN * 64; idx += 256) {
        int k = idx >> 6, f = idx & 63;
        Bs[k][f] = W[idx];
    }
    // load A tile (transposed into As[k][node])
    if (FIN == 64) {
#pragma unroll
        for (int r = 0; r < 4; r++) {
            int q = t + 256 * r;         // 0..1023 float4 slots
            int node = q >> 4;           // 0..63
            int k4 = q & 15;
            int gn = n0 + node;
            float4 v = (gn < N) ? *(const float4*)(A + (size_t)gn * 64 + 4 * k4)
                                : make_float4(0.f, 0.f, 0.f, 0.f);
            As[4 * k4 + 0][node] = v.x;
            As[4 * k4 + 1][node] = v.y;
            As[4 * k4 + 2][node] = v.z;
            As[4 * k4 + 3][node] = v.w;
        }
    } else {
        for (int idx = t; idx < 64 * FIN; idx += 256) {
            int node = idx / FIN;
            int k = idx % FIN;
            int gn = n0 + node;
            As[k][node] = (gn < N) ? A[(size_t)gn * FIN + k] : 0.f;
        }
    }
    __syncthreads();

    int tx = t & 15, ty = t >> 4;        // tx: feature quad, ty: node quad
    float acc[4][4];
#pragma unroll
    for (int i = 0; i < 4; i++)
#pragma unroll
        for (int j = 0; j < 4; j++) acc[i][j] = 0.f;

#pragma unroll 8
    for (int k = 0; k < FIN; k++) {
        float4 a = *(const float4*)&As[k][4 * ty];
        float4 b = *(const float4*)&Bs[k][4 * tx];
        float av[4] = {a.x, a.y, a.z, a.w};
        float bv[4] = {b.x, b.y, b.z, b.w};
#pragma unroll
        for (int i = 0; i < 4; i++)
#pragma unroll
            for (int j = 0; j < 4; j++) acc[i][j] += av[i] * bv[j];
    }

#pragma unroll
    for (int i = 0; i < 4; i++) {
        int gn = n0 + 4 * ty + i;
        if (gn < N) {
            __half2 p0 = __floats2half2_rn(acc[i][0], acc[i][1]);
            __half2 p1 = __floats2half2_rn(acc[i][2], acc[i][3]);
            uint2 pk;
            pk.x = *(unsigned*)&p0;
            pk.y = *(unsigned*)&p1;
            *(uint2*)(C + (size_t)gn * 64 + 4 * tx) = pk;   // 8B-aligned
        }
    }
}

// ------------------------------- aggregation -------------------------------
// One warp per node; lane holds 2 features as one half2. fp32 accumulation.
// Edge lists loaded as int4/float4 (warp-uniform LDG.128) with peeling.
// act: 1=relu, 2=sigmoid.

__global__ void k_agg(const __half2* __restrict__ tin,
                      const float* __restrict__ bias,
                      float* __restrict__ out, int N, int act) {
    int w = (blockIdx.x * blockDim.x + threadIdx.x) >> 5;
    int lane = threadIdx.x & 31;
    if (w >= N) return;

    float2 self = __half22float2(tin[(size_t)w * 32 + lane]);
    float sn = g_selfnorm[w];
    float ax = sn * self.x;
    float ay = sn * self.y;

    int beg = g_rowoff[w];
    int end = g_rowoff[w + 1];
    int j = beg;

    // peel to 16B alignment of g_esrc[j]
    int jal = (beg + 3) & ~3;
    if (jal > end) jal = end;
    for (; j < jal; j++) {
        int s = g_esrc[j];
        float m = g_enorm[j];
        float2 v = __half22float2(tin[(size_t)s * 32 + lane]);
        ax += m * v.x; ay += m * v.y;
    }
    // vectorized body: 2 uniform LDG.128 + 4 gathers per 4 edges
    for (; j + 4 <= end; j += 4) {
        int4   s4 = *(const int4*)&g_esrc[j];
        float4 m4 = *(const float4*)&g_enorm[j];
        float2 v0 = __half22float2(tin[(size_t)s4.x * 32 + lane]);
        float2 v1 = __half22float2(tin[(size_t)s4.y * 32 + lane]);
        float2 v2 = __half22float2(tin[(size_t)s4.z * 32 + lane]);
        float2 v3 = __half22float2(tin[(size_t)s4.w * 32 + lane]);
        ax += m4.x * v0.x; ay += m4.x * v0.y;
        ax += m4.y * v1.x; ay += m4.y * v1.y;
        ax += m4.z * v2.x; ay += m4.z * v2.y;
        ax += m4.w * v3.x; ay += m4.w * v3.y;
    }
    // tail
    for (; j < end; j++) {
        int s = g_esrc[j];
        float m = g_enorm[j];
        float2 v = __half22float2(tin[(size_t)s * 32 + lane]);
        ax += m * v.x; ay += m * v.y;
    }

    float2 b = ((const float2*)bias)[lane];
    ax += b.x; ay += b.y;
    if (act == 1) {
        ax = fmaxf(ax, 0.f);
        ay = fmaxf(ay, 0.f);
    } else if (act == 2) {
        ax = 1.0f / (1.0f + __expf(-ax));
        ay = 1.0f / (1.0f + __expf(-ay));
    }
    ((float2*)out)[(size_t)w * 32 + lane] = make_float2(ax, ay);
}

// --------------------------------- launcher --------------------------------

extern "C" void kernel_launch(void* const* d_in, const int* in_sizes, int n_in,
                              void* d_out, int out_size) {
    const float* x  = (const float*)d_in[0];
    const int*   ei = (const int*)d_in[1];     // int32 (JAX default, x64 off)
    const float* ew = (const float*)d_in[2];
    const float* W0 = (const float*)d_in[3];
    const float* b0 = (const float*)d_in[4];
    const float* Wm = (const float*)d_in[5];
    const float* bm = (const float*)d_in[6];
    const float* Wl = (const float*)d_in[7];
    const float* bl = (const float*)d_in[8];

    int N = in_sizes[0] / 15;
    int E = in_sizes[2];

    __half* t;
    float*  h;
    cudaGetSymbolAddress((void**)&t, g_t);
    cudaGetSymbolAddress((void**)&h, g_h);

    int NB = (N + 1023) / 1024;

    k_init<<<(N + 255) / 256, 256>>>(N);
    k_edge_deg<<<(E + 255) / 256, 256>>>(ei, ew, E, N);
    k_dinv<<<(N + 255) / 256, 256>>>(N);
    k_scan_reduce<<<NB, 256>>>(N);
    k_scan_bsum<<<1, 128>>>(NB, N, E);
    k_scan_chunks<<<NB, 256>>>(N);
    k_fill<<<(E + 255) / 256, 256>>>(ei, ew, E, N);

    // layer 0: agg(x @ W0) + b0, relu   (transform first: 15 -> 64)
    k_transform<15><<<(N + 63) / 64, 256>>>(x, W0, t, N);
    k_agg<<<(N + 7) / 8, 256>>>((const __half2*)t, b0, h, N, 1);

    // middle layers 1..6
    for (int i = 0; i < 6; i++) {
        k_transform<64><<<(N + 63) / 64, 256>>>(h, Wm + (size_t)i * 64 * 64, t, N);
        k_agg<<<(N + 7) / 8, 256>>>((const __half2*)t, bm + (size_t)i * 64, h, N, 1);
    }

    // final layer + sigmoid -> d_out
    k_transform<64><<<(N + 63) / 64, 256>>>(h, Wl, t, N);
    k_agg<<<(N + 7) / 8, 256>>>((const __half2*)t, bl, (float*)d_out, N, 2);
}

// round 7
// speedup vs baseline: 1.3756x; 1.3756x over previous
#include <cuda_runtime.h>
#include <cuda_fp16.h>
#include <cstdint>

// ---------------------------------------------------------------------------
// GCNEncoder: 8-layer GCN, N=100000, E=1.6M, F=15->64(x7)->64
// h stored fp16; mid/final transforms = HMMA tensor-core GEMM (fp32 accum);
// agg = round-5 scalar CSR gather (fp16 payload, fp32 accum).
// edge_index is int32 on device (JAX default, x64 disabled).
// ---------------------------------------------------------------------------

#define MAXN 131072
#define MAXE 1700000

__device__ __half g_t[MAXN * 64];        // transformed features (fp16)
__device__ __half g_hh[MAXN * 64];       // activations (fp16)
__device__ __half g_wh[7 * 4096];        // fp16 weights: Wm[0..5], Wl
__device__ float  g_deg[MAXN];
__device__ float  g_dinv[MAXN];
__device__ float  g_selfnorm[MAXN];
__device__ int    g_cnt[MAXN];
__device__ int    g_cursor[MAXN];
__device__ int    g_rowoff[MAXN + 1];
__device__ int    g_bsum[256];
__device__ int    g_esrc[MAXE];
__device__ float  g_enorm[MAXE];

// ------------------------------ preprocessing ------------------------------

__global__ void k_init(int N) {
    int i = blockIdx.x * blockDim.x + threadIdx.x;
    if (i < N) {
        g_deg[i] = 1.0f;   // self-loop weight
        g_cnt[i] = 0;
        g_cursor[i] = 0;
    }
}

__global__ void k_wconv(const float* __restrict__ Wm,
                        const float* __restrict__ Wl) {
    int i = blockIdx.x * blockDim.x + threadIdx.x;
    if (i < 6 * 4096)      g_wh[i] = __float2half(Wm[i]);
    else if (i < 7 * 4096) g_wh[i] = __float2half(Wl[i - 6 * 4096]);
}

__global__ void k_edge_deg(const int* __restrict__ ei,
                           const float* __restrict__ ew, int E, int N) {
    int i = blockIdx.x * blockDim.x + threadIdx.x;
    if (i >= E) return;
    int d = ei[E + i];
    if ((unsigned)d >= (unsigned)N) return;
    atomicAdd(&g_deg[d], ew[i]);
    atomicAdd(&g_cnt[d], 1);
}

__global__ void k_dinv(int N) {
    int i = blockIdx.x * blockDim.x + threadIdx.x;
    if (i < N) {
        float dg = g_deg[i];
        float r = (dg > 0.0f) ? rsqrtf(dg) : 0.0f;
        g_dinv[i] = r;
        g_selfnorm[i] = r * r;
    }
}

// scan step A: per-1024-chunk sums
__global__ void k_scan_reduce(int N) {
    __shared__ int sdata[256];
    int b = blockIdx.x;
    int base = b * 1024;
    int sum = 0;
    for (int i = threadIdx.x; i < 1024; i += 256) {
        int g = base + i;
        sum += (g < N) ? g_cnt[g] : 0;
    }
    sdata[threadIdx.x] = sum;
    __syncthreads();
    for (int s = 128; s > 0; s >>= 1) {
        if (threadIdx.x < s) sdata[threadIdx.x] += sdata[threadIdx.x + s];
        __syncthreads();
    }
    if (threadIdx.x == 0) g_bsum[b] = sdata[0];
}

// scan step B: exclusive scan of chunk sums (NB <= 128)
__global__ void k_scan_bsum(int NB, int N, int E) {
    __shared__ int sh[128];
    int t = threadIdx.x;
    if (t < NB) sh[t] = g_bsum[t];
    __syncthreads();
    if (t == 0) {
        int run = 0;
        for (int i = 0; i < NB; i++) { int x = sh[i]; sh[i] = run; run += x; }
    }
    __syncthreads();
    if (t < NB) g_bsum[t] = sh[t];
    if (t == 0) g_rowoff[N] = E;
}

// scan step C: per-chunk exclusive scan + chunk base -> row offsets
__global__ void k_scan_chunks(int N) {
    int b = blockIdx.x;
    int t = threadIdx.x;
    int g0 = b * 1024 + 4 * t;
    int v0 = (g0 + 0 < N) ? g_cnt[g0 + 0] : 0;
    int v1 = (g0 + 1 < N) ? g_cnt[g0 + 1] : 0;
    int v2 = (g0 + 2 < N) ? g_cnt[g0 + 2] : 0;
    int v3 = (g0 + 3 < N) ? g_cnt[g0 + 3] : 0;
    int s = v0 + v1 + v2 + v3;
    int lane = t & 31, wid = t >> 5;
    int incl = s;
#pragma unroll
    for (int o = 1; o < 32; o <<= 1) {
        int x = __shfl_up_sync(0xffffffffu, incl, o);
        if (lane >= o) incl += x;
    }
    __shared__ int wsum[8];
    __shared__ int woff[8];
    if (lane == 31) wsum[wid] = incl;
    __syncthreads();
    if (t == 0) {
        int run = 0;
        for (int i = 0; i < 8; i++) { int x = wsum[i]; woff[i] = run; run += x; }
    }
    __syncthreads();
    int excl = g_bsum[b] + woff[wid] + (incl - s);
    if (g0 + 0 < N) g_rowoff[g0 + 0] = excl;
    if (g0 + 1 < N) g_rowoff[g0 + 1] = excl + v0;
    if (g0 + 2 < N) g_rowoff[g0 + 2] = excl + v0 + v1;
    if (g0 + 3 < N) g_rowoff[g0 + 3] = excl + v0 + v1 + v2;
}

__global__ void k_fill(const int* __restrict__ ei,
                       const float* __restrict__ ew, int E, int N) {
    int i = blockIdx.x * blockDim.x + threadIdx.x;
    if (i >= E) return;
    int s = ei[i];
    int d = ei[E + i];
    if ((unsigned)s >= (unsigned)N || (unsigned)d >= (unsigned)N) return;
    float nm = g_dinv[s] * ew[i] * g_dinv[d];
    int pos = g_rowoff[d] + atomicAdd(&g_cursor[d], 1);
    if ((unsigned)pos < (unsigned)MAXE) {
        g_esrc[pos] = s;
        g_enorm[pos] = nm;
    }
}

// ------------------------- layer-0 transform (SIMT) -------------------------
// C[N,64] = x[N,15] @ W0[15,64], fp32 compute, fp16 store.

__global__ void k_transform0(const float* __restrict__ A,
                             const float* __restrict__ W,
                             __half* __restrict__ C, int N) {
    __shared__ float As[15][68];
    __shared__ float Bs[15][68];
    int t = threadIdx.x;                 // 256 threads
    int n0 = blockIdx.x * 64;

    for (int idx = t; idx < 15 * 64; idx += 256) {
        int k = idx >> 6, f = idx & 63;
        Bs[k][f] = W[idx];
    }
    for (int idx = t; idx < 64 * 15; idx += 256) {
        int node = idx / 15;
        int k = idx % 15;
        int gn = n0 + node;
        As[k][node] = (gn < N) ? A[(size_t)gn * 15 + k] : 0.f;
    }
    __syncthreads();

    int tx = t & 15, ty = t >> 4;
    float acc[4][4];
#pragma unroll
    for (int i = 0; i < 4; i++)
#pragma unroll
        for (int j = 0; j < 4; j++) acc[i][j] = 0.f;

#pragma unroll
    for (int k = 0; k < 15; k++) {
        float4 a = *(const float4*)&As[k][4 * ty];
        float4 b = *(const float4*)&Bs[k][4 * tx];
        float av[4] = {a.x, a.y, a.z, a.w};
        float bv[4] = {b.x, b.y, b.z, b.w};
#pragma unroll
        for (int i = 0; i < 4; i++)
#pragma unroll
            for (int j = 0; j < 4; j++) acc[i][j] += av[i] * bv[j];
    }

#pragma unroll
    for (int i = 0; i < 4; i++) {
        int gn = n0 + 4 * ty + i;
        if (gn < N) {
            __half2 p0 = __floats2half2_rn(acc[i][0], acc[i][1]);
            __half2 p1 = __floats2half2_rn(acc[i][2], acc[i][3]);
            uint2 pk;
            pk.x = *(unsigned*)&p0;
            pk.y = *(unsigned*)&p1;
            *(uint2*)(C + (size_t)gn * 64 + 4 * tx) = pk;
        }
    }
}

// ---------------------- mid/final transform (tensor core) -------------------
// C[N,64] = A[N,64] @ W[64,64]; A,W fp16, fp32 accum via mma.m16n8k16.
// Block: 256 thr (8 warps), 128-node tile; warp computes 16x64.

__device__ __forceinline__ void mma16816(float c[4], unsigned a0, unsigned a1,
                                         unsigned a2, unsigned a3,
                                         unsigned b0, unsigned b1) {
    asm volatile(
        "mma.sync.aligned.m16n8k16.row.col.f32.f16.f16.f32 "
        "{%0,%1,%2,%3}, {%4,%5,%6,%7}, {%8,%9}, {%0,%1,%2,%3};\n"
        : "+f"(c[0]), "+f"(c[1]), "+f"(c[2]), "+f"(c[3])
        : "r"(a0), "r"(a1), "r"(a2), "r"(a3), "r"(b0), "r"(b1));
}

__global__ void __launch_bounds__(256) k_transform_tc(
    const __half* __restrict__ A,      // [N,64] fp16
    const __half* __restrict__ Wh,     // [64,64] fp16, k-major
    __half* __restrict__ C, int N)
{
    __shared__ __align__(16) __half As[128 * 72];   // row stride 72 halves
    __shared__ __align__(16) __half Wt[64 * 72];    // transposed [n][k]

    int tid = threadIdx.x;
    int n0 = blockIdx.x * 128;

    for (int i = tid; i < 4096; i += 256) {
        int k = i >> 6, n = i & 63;
        Wt[n * 72 + k] = Wh[i];
    }
    {
        const uint4* Ag = (const uint4*)A;   // 8 uint4 per 64-half row
#pragma unroll
        for (int r4 = 0; r4 < 4; r4++) {
            int q = tid + 256 * r4;          // 0..1023
            int r = q >> 3, u = q & 7;
            int gr = n0 + r;
            uint4 v = (gr < N) ? Ag[(size_t)gr * 8 + u]
                               : make_uint4(0u, 0u, 0u, 0u);
            *(uint4*)&As[r * 72 + u * 8] = v;
        }
    }
    __syncthreads();

    int lane = tid & 31, warp = tid >> 5;
    int g = lane >> 2, t = lane & 3;
    int m0 = warp * 16;

    float acc[8][4];
#pragma unroll
    for (int i = 0; i < 8; i++)
#pragma unroll
        for (int j = 0; j < 4; j++) acc[i][j] = 0.f;

    const unsigned* As2 = (const unsigned*)As;   // stride 36 uints
    const unsigned* Wt2 = (const unsigned*)Wt;

#pragma unroll
    for (int ks = 0; ks < 4; ks++) {
        int k8 = ks * 8;                         // k offset in uints
        unsigned a0 = As2[(m0 + g) * 36 + k8 + t];
        unsigned a1 = As2[(m0 + g + 8) * 36 + k8 + t];
        unsigned a2 = As2[(m0 + g) * 36 + k8 + 4 + t];
        unsigned a3 = As2[(m0 + g + 8) * 36 + k8 + 4 + t];
#pragma unroll
        for (int nt = 0; nt < 8; nt++) {
            unsigned b0 = Wt2[(nt * 8 + g) * 36 + k8 + t];
            unsigned b1 = Wt2[(nt * 8 + g) * 36 + k8 + 4 + t];
            mma16816(acc[nt], a0, a1, a2, a3, b0, b1);
        }
    }

    __half2* Cv = (__half2*)C;                   // 32 half2 per row
    int r0 = n0 + m0 + g;
    int r1 = r0 + 8;
#pragma unroll
    for (int nt = 0; nt < 8; nt++) {
        if (r0 < N) Cv[(size_t)r0 * 32 + nt * 4 + t] =
            __floats2half2_rn(acc[nt][0], acc[nt][1]);
        if (r1 < N) Cv[(size_t)r1 * 32 + nt * 4 + t] =
            __floats2half2_rn(acc[nt][2], acc[nt][3]);
    }
}

// ------------------------------- aggregation -------------------------------
// One warp per node; lane holds 2 features as one half2. fp32 accumulation.
// FP16OUT: write fp16 h; else fp32 (final layer -> d_out).

template <bool FP16OUT>
__global__ void k_agg(const __half2* __restrict__ tin,
                      const float* __restrict__ bias,
                      void* __restrict__ outp, int N, int act) {
    int w = (blockIdx.x * blockDim.x + threadIdx.x) >> 5;
    int lane = threadIdx.x & 31;
    if (w >= N) return;

    float2 self = __half22float2(tin[(size_t)w * 32 + lane]);
    float sn = g_selfnorm[w];
    float ax = sn * self.x;
    float ay = sn * self.y;

    int beg = g_rowoff[w];
    int end = g_rowoff[w + 1];
    int j = beg;
    for (; j + 4 <= end; j += 4) {
        int s0 = g_esrc[j + 0], s1 = g_esrc[j + 1];
        int s2 = g_esrc[j + 2], s3 = g_esrc[j + 3];
        float m0 = g_enorm[j + 0], m1 = g_enorm[j + 1];
        float m2 = g_enorm[j + 2], m3 = g_enorm[j + 3];
        float2 v0 = __half22float2(tin[(size_t)s0 * 32 + lane]);
        float2 v1 = __half22float2(tin[(size_t)s1 * 32 + lane]);
        float2 v2 = __half22float2(tin[(size_t)s2 * 32 + lane]);
        float2 v3 = __half22float2(tin[(size_t)s3 * 32 + lane]);
        ax += m0 * v0.x; ay += m0 * v0.y;
        ax += m1 * v1.x; ay += m1 * v1.y;
        ax += m2 * v2.x; ay += m2 * v2.y;
        ax += m3 * v3.x; ay += m3 * v3.y;
    }
    for (; j < end; j++) {
        int s = g_esrc[j];
        float m = g_enorm[j];
        float2 v = __half22float2(tin[(size_t)s * 32 + lane]);
        ax += m * v.x; ay += m * v.y;
    }

    float2 b = ((const float2*)bias)[lane];
    ax += b.x; ay += b.y;
    if (act == 1) {
        ax = fmaxf(ax, 0.f);
        ay = fmaxf(ay, 0.f);
    } else {
        ax = 1.0f / (1.0f + __expf(-ax));
        ay = 1.0f / (1.0f + __expf(-ay));
    }
    if (FP16OUT) {
        ((__half2*)outp)[(size_t)w * 32 + lane] = __floats2half2_rn(ax, ay);
    } else {
        ((float2*)outp)[(size_t)w * 32 + lane] = make_float2(ax, ay);
    }
}

// --------------------------------- launcher --------------------------------

extern "C" void kernel_launch(void* const* d_in, const int* in_sizes, int n_in,
                              void* d_out, int out_size) {
    const float* x  = (const float*)d_in[0];
    const int*   ei = (const int*)d_in[1];     // int32 (JAX default, x64 off)
    const float* ew = (const float*)d_in[2];
    const float* W0 = (const float*)d_in[3];
    const float* b0 = (const float*)d_in[4];
    const float* Wm = (const float*)d_in[5];
    const float* bm = (const float*)d_in[6];
    const float* Wl = (const float*)d_in[7];
    const float* bl = (const float*)d_in[8];

    int N = in_sizes[0] / 15;
    int E = in_sizes[2];

    __half* t;
    __half* h;
    __half* wh;
    cudaGetSymbolAddress((void**)&t, g_t);
    cudaGetSymbolAddress((void**)&h, g_hh);
    cudaGetSymbolAddress((void**)&wh, g_wh);

    int NB = (N + 1023) / 1024;

    k_init<<<(N + 255) / 256, 256>>>(N);
    k_wconv<<<(7 * 4096 + 255) / 256, 256>>>(Wm, Wl);
    k_edge_deg<<<(E + 255) / 256, 256>>>(ei, ew, E, N);
    k_dinv<<<(N + 255) / 256, 256>>>(N);
    k_scan_reduce<<<NB, 256>>>(N);
    k_scan_bsum<<<1, 128>>>(NB, N, E);
    k_scan_chunks<<<NB, 256>>>(N);
    k_fill<<<(E + 255) / 256, 256>>>(ei, ew, E, N);

    int gT = (N + 127) / 128;
    int gA = (N + 7) / 8;

    // layer 0: h = relu(agg(x @ W0) + b0)
    k_transform0<<<(N + 63) / 64, 256>>>(x, W0, t, N);
    k_agg<true><<<gA, 256>>>((const __half2*)t, b0, h, N, 1);

    // middle layers 1..6 (tensor-core transform)
    for (int i = 0; i < 6; i++) {
        k_transform_tc<<<gT, 256>>>(h, wh + (size_t)i * 4096, t, N);
        k_agg<true><<<gA, 256>>>((const __half2*)t, bm + (size_t)i * 64, h, N, 1);
    }

    // final layer + sigmoid -> d_out (fp32)
    k_transform_tc<<<gT, 256>>>(h, wh + (size_t)6 * 4096, t, N);
    k_agg<false><<<gA, 256>>>((const __half2*)t, bl, d_out, N, 2);
}